// round 1
// baseline (speedup 1.0000x reference)
#include <cuda_runtime.h>
#include <math.h>

#define BSZ 4
#define SEQ 2048
#define EMB 1024
#define NH 16
#define HD 64
#define MTOT (BSZ*SEQ)   // 8192

// Scratch (allocation-free rule: __device__ globals). 4 x 32 MB.
static __device__ __align__(128) float g_Q[(size_t)MTOT*EMB];
static __device__ __align__(128) float g_K[(size_t)MTOT*EMB];
static __device__ __align__(128) float g_V[(size_t)MTOT*EMB];
static __device__ __align__(128) float g_AO[(size_t)MTOT*EMB];

// ---------------------------------------------------------------------------
// C = A(M x 1024) @ W(1024 x 1024) + bias.
// HEADOUT=1: write C into [B, H, S, D] layout (for Q/K/V).
// HEADOUT=0: plain row-major [M, 1024].
// 128x128x16 tile, 256 threads, 8x8 microtile.
// ---------------------------------------------------------------------------
template<int HEADOUT>
__global__ __launch_bounds__(256)
void gemm_bias_kernel(const float* __restrict__ A, const float* __restrict__ W,
                      const float* __restrict__ bias, float* __restrict__ C) {
    __shared__ float As[16][132];   // [k][m]
    __shared__ float Bs[16][132];   // [k][n]
    const int t  = threadIdx.x;
    const int tx = t & 15, ty = t >> 4;
    const int m0 = blockIdx.y << 7;
    const int n0 = blockIdx.x << 7;
    const int lA_r = t >> 2,  lA_k = (t & 3)  << 2;
    const int lB_k = t >> 5,  lB_n = (t & 31) << 2;

    float acc[8][8];
#pragma unroll
    for (int i = 0; i < 8; i++)
#pragma unroll
        for (int j = 0; j < 8; j++) acc[i][j] = 0.f;

    for (int k0 = 0; k0 < EMB; k0 += 16) {
#pragma unroll
        for (int r = 0; r < 128; r += 64) {
            float4 v = *(const float4*)(A + (size_t)(m0 + lA_r + r)*EMB + k0 + lA_k);
            As[lA_k+0][lA_r+r] = v.x;
            As[lA_k+1][lA_r+r] = v.y;
            As[lA_k+2][lA_r+r] = v.z;
            As[lA_k+3][lA_r+r] = v.w;
        }
#pragma unroll
        for (int r = 0; r < 16; r += 8) {
            float4 v = *(const float4*)(W + (size_t)(k0 + lB_k + r)*EMB + n0 + lB_n);
            *(float4*)&Bs[lB_k + r][lB_n] = v;
        }
        __syncthreads();
#pragma unroll
        for (int k = 0; k < 16; k++) {
            float a[8], b[8];
            *(float4*)&a[0] = *(const float4*)&As[k][ty*8];
            *(float4*)&a[4] = *(const float4*)&As[k][ty*8+4];
            *(float4*)&b[0] = *(const float4*)&Bs[k][tx*8];
            *(float4*)&b[4] = *(const float4*)&Bs[k][tx*8+4];
#pragma unroll
            for (int i = 0; i < 8; i++)
#pragma unroll
                for (int j = 0; j < 8; j++)
                    acc[i][j] = fmaf(a[i], b[j], acc[i][j]);
        }
        __syncthreads();
    }

    float br[8];
#pragma unroll
    for (int j = 0; j < 8; j++) br[j] = bias[n0 + tx*8 + j];

#pragma unroll
    for (int i = 0; i < 8; i++) {
        int m = m0 + ty*8 + i;
        int bb = m / SEQ, s = m % SEQ;
#pragma unroll
        for (int jj = 0; jj < 8; jj += 4) {
            int n = n0 + tx*8 + jj;
            float4 v;
            v.x = acc[i][jj+0] + br[jj+0];
            v.y = acc[i][jj+1] + br[jj+1];
            v.z = acc[i][jj+2] + br[jj+2];
            v.w = acc[i][jj+3] + br[jj+3];
            if (HEADOUT) {
                int h = n >> 6, d = n & 63;
                *(float4*)(C + (((size_t)bb*NH + h)*SEQ + s)*HD + d) = v;
            } else {
                *(float4*)(C + (size_t)m*EMB + n) = v;
            }
        }
    }
}

// ---------------------------------------------------------------------------
// Flash attention, fp32. One block = 64 queries of one (b, h).
// 256 threads: tx = t&15 (16 col-groups of 4), ty = t>>4 (16 row-groups of 4).
// Online softmax, exact -1e9 mask select (matches reference semantics).
// Output written to g_AO in [B, S, E] layout ready for the O-projection GEMM.
// ---------------------------------------------------------------------------
__global__ __launch_bounds__(256)
void attn_kernel(const int* __restrict__ mask) {
    extern __shared__ float sm[];
    float* Qs = sm;               // [d][q]  64 x 68
    float* Ks = sm + 64*68;       // [d][k]
    float* Vs = sm + 2*64*68;     // [k][d]
    float* Ps = sm + 3*64*68;     // [k][q]
    __shared__ int msk[64];

    const int t  = threadIdx.x;
    const int tx = t & 15, ty = t >> 4;
    const int qb = blockIdx.x, h = blockIdx.y, b = blockIdx.z;

    const float* Qg = g_Q + (((size_t)b*NH + h)*SEQ + (size_t)qb*64)*HD;
    const float* Kg = g_K + ((size_t)b*NH + h)*SEQ*HD;
    const float* Vg = g_V + ((size_t)b*NH + h)*SEQ*HD;
    const int*   mg = mask + b*SEQ;

    const int lr = t >> 4, ld = (t & 15) << 2;
#pragma unroll
    for (int rr = 0; rr < 64; rr += 16) {
        float4 v = *(const float4*)(Qg + (size_t)(lr+rr)*HD + ld);
        Qs[(ld+0)*68 + lr+rr] = v.x;
        Qs[(ld+1)*68 + lr+rr] = v.y;
        Qs[(ld+2)*68 + lr+rr] = v.z;
        Qs[(ld+3)*68 + lr+rr] = v.w;
    }

    float o[4][4];
#pragma unroll
    for (int i = 0; i < 4; i++)
#pragma unroll
        for (int j = 0; j < 4; j++) o[i][j] = 0.f;
    float mrow[4] = {-INFINITY, -INFINITY, -INFINITY, -INFINITY};
    float lrow[4] = {0.f, 0.f, 0.f, 0.f};

    for (int kb = 0; kb < SEQ/64; kb++) {
        __syncthreads();   // protect Ks/Vs/Ps from previous iteration readers
        const float* Kt = Kg + (size_t)kb*64*HD;
        const float* Vt = Vg + (size_t)kb*64*HD;
#pragma unroll
        for (int rr = 0; rr < 64; rr += 16) {
            float4 kv = *(const float4*)(Kt + (size_t)(lr+rr)*HD + ld);
            Ks[(ld+0)*68 + lr+rr] = kv.x;
            Ks[(ld+1)*68 + lr+rr] = kv.y;
            Ks[(ld+2)*68 + lr+rr] = kv.z;
            Ks[(ld+3)*68 + lr+rr] = kv.w;
            float4 vv = *(const float4*)(Vt + (size_t)(lr+rr)*HD + ld);
            *(float4*)&Vs[(lr+rr)*68 + ld] = vv;
        }
        if (t < 64) msk[t] = mg[kb*64 + t];
        __syncthreads();

        // S = Q K^T (4x4 per thread, outer product over d)
        float s4[4][4];
#pragma unroll
        for (int i = 0; i < 4; i++)
#pragma unroll
            for (int j = 0; j < 4; j++) s4[i][j] = 0.f;
#pragma unroll
        for (int d = 0; d < 64; d++) {
            float a[4], bb[4];
            *(float4*)a  = *(const float4*)&Qs[d*68 + ty*4];
            *(float4*)bb = *(const float4*)&Ks[d*68 + tx*4];
#pragma unroll
            for (int i = 0; i < 4; i++)
#pragma unroll
                for (int j = 0; j < 4; j++)
                    s4[i][j] = fmaf(a[i], bb[j], s4[i][j]);
        }

        // scale + mask (exact -1e9 select, like the reference)
#pragma unroll
        for (int j = 0; j < 4; j++) {
            bool on = (msk[tx*4 + j] != 0);
#pragma unroll
            for (int i = 0; i < 4; i++)
                s4[i][j] = on ? s4[i][j]*0.125f : -1.0e9f;
        }

        // online softmax per query row; row spans 16 lanes (tx) in-warp
#pragma unroll
        for (int i = 0; i < 4; i++) {
            float rm = fmaxf(fmaxf(s4[i][0], s4[i][1]), fmaxf(s4[i][2], s4[i][3]));
#pragma unroll
            for (int off = 1; off < 16; off <<= 1)
                rm = fmaxf(rm, __shfl_xor_sync(0xffffffffu, rm, off));
            float mn = fmaxf(mrow[i], rm);
            float sc = __expf(mrow[i] - mn);
            mrow[i] = mn;
            float p[4]; float rs = 0.f;
#pragma unroll
            for (int j = 0; j < 4; j++) { p[j] = __expf(s4[i][j] - mn); rs += p[j]; }
#pragma unroll
            for (int off = 1; off < 16; off <<= 1)
                rs += __shfl_xor_sync(0xffffffffu, rs, off);
            lrow[i] = lrow[i]*sc + rs;
#pragma unroll
            for (int j = 0; j < 4; j++) {
                o[i][j] *= sc;
                Ps[(tx*4+j)*68 + ty*4 + i] = p[j];   // transposed store [k][q]
            }
        }
        __syncthreads();

        // O += P V (outer product over k)
#pragma unroll
        for (int k = 0; k < 64; k++) {
            float a[4], bb[4];
            *(float4*)a  = *(const float4*)&Ps[k*68 + ty*4];
            *(float4*)bb = *(const float4*)&Vs[k*68 + tx*4];
#pragma unroll
            for (int i = 0; i < 4; i++)
#pragma unroll
                for (int j = 0; j < 4; j++)
                    o[i][j] = fmaf(a[i], bb[j], o[i][j]);
        }
    }

    // normalize and write [B, S, E] (E = h*64 + d)
    float* Og = g_AO + ((size_t)b*SEQ + (size_t)qb*64)*EMB + h*HD;
#pragma unroll
    for (int i = 0; i < 4; i++) {
        float inv = 1.0f / lrow[i];
        int s_ = ty*4 + i;
        float4 v;
        v.x = o[i][0]*inv; v.y = o[i][1]*inv; v.z = o[i][2]*inv; v.w = o[i][3]*inv;
        *(float4*)(Og + (size_t)s_*EMB + tx*4) = v;
    }
}

// ---------------------------------------------------------------------------
extern "C" void kernel_launch(void* const* d_in, const int* in_sizes, int n_in,
                              void* d_out, int out_size) {
    const float* x  = (const float*)d_in[0];
    const int*  mask = (const int*)d_in[1];
    const float* Wq = (const float*)d_in[2];
    const float* bq = (const float*)d_in[3];
    const float* Wk = (const float*)d_in[4];
    const float* bk = (const float*)d_in[5];
    const float* Wv = (const float*)d_in[6];
    const float* bv = (const float*)d_in[7];
    const float* Wo = (const float*)d_in[8];
    const float* bo = (const float*)d_in[9];

    float *Q, *K, *V, *AO;
    cudaGetSymbolAddress((void**)&Q,  g_Q);
    cudaGetSymbolAddress((void**)&K,  g_K);
    cudaGetSymbolAddress((void**)&V,  g_V);
    cudaGetSymbolAddress((void**)&AO, g_AO);

    dim3 gg(EMB/128, MTOT/128);   // (8, 64)
    gemm_bias_kernel<1><<<gg, 256>>>(x, Wq, bq, Q);
    gemm_bias_kernel<1><<<gg, 256>>>(x, Wk, bk, K);
    gemm_bias_kernel<1><<<gg, 256>>>(x, Wv, bv, V);

    const int asm_bytes = 4*64*68*4;  // 69632
    cudaFuncSetAttribute(attn_kernel,
                         cudaFuncAttributeMaxDynamicSharedMemorySize, asm_bytes);
    attn_kernel<<<dim3(SEQ/64, NH, BSZ), 256, asm_bytes>>>(mask);

    gemm_bias_kernel<0><<<gg, 256>>>(AO, Wo, bo, (float*)d_out);
}

// round 4
// speedup vs baseline: 2.7687x; 2.7687x over previous
#include <cuda_runtime.h>
#include <cuda_bf16.h>
#include <math.h>
#include <stdint.h>

#define BSZ 4
#define SEQ 2048
#define EMB 1024
#define NH 16
#define HD 64
#define MTOT (BSZ*SEQ)   // 8192

// ---------------- scratch (__device__ globals; no allocs allowed) ----------
static __device__ __align__(256) __nv_bfloat16 g_xh[(size_t)MTOT*EMB];
static __device__ __align__(256) __nv_bfloat16 g_xl[(size_t)MTOT*EMB];
static __device__ __align__(256) __nv_bfloat16 g_wh[4][(size_t)EMB*EMB];
static __device__ __align__(256) __nv_bfloat16 g_wl[4][(size_t)EMB*EMB];
static __device__ __align__(256) __nv_bfloat16 g_Qh[(size_t)MTOT*EMB];
static __device__ __align__(256) __nv_bfloat16 g_Ql[(size_t)MTOT*EMB];
static __device__ __align__(256) __nv_bfloat16 g_Kh[(size_t)MTOT*EMB];
static __device__ __align__(256) __nv_bfloat16 g_Kl[(size_t)MTOT*EMB];
static __device__ __align__(256) __nv_bfloat16 g_Vh[(size_t)MTOT*EMB];
static __device__ __align__(256) __nv_bfloat16 g_Vl[(size_t)MTOT*EMB];

// ---------------- helpers --------------------------------------------------
__device__ __forceinline__ uint32_t smem_u32(const void* p) {
    uint32_t a;
    asm("{ .reg .u64 t; cvta.to.shared.u64 t, %1; cvt.u32.u64 %0, t; }"
        : "=r"(a) : "l"(p));
    return a;
}
__device__ __forceinline__ void ldsm4(uint32_t r[4], uint32_t a) {
    asm volatile("ldmatrix.sync.aligned.m8n8.x4.shared.b16 {%0,%1,%2,%3}, [%4];"
        : "=r"(r[0]), "=r"(r[1]), "=r"(r[2]), "=r"(r[3]) : "r"(a));
}
__device__ __forceinline__ void ldsm4t(uint32_t r[4], uint32_t a) {
    asm volatile("ldmatrix.sync.aligned.m8n8.x4.trans.shared.b16 {%0,%1,%2,%3}, [%4];"
        : "=r"(r[0]), "=r"(r[1]), "=r"(r[2]), "=r"(r[3]) : "r"(a));
}
__device__ __forceinline__ void mma16816(float c[4], const uint32_t a[4],
                                         uint32_t b0, uint32_t b1) {
    asm volatile("mma.sync.aligned.m16n8k16.row.col.f32.bf16.bf16.f32 "
        "{%0,%1,%2,%3}, {%4,%5,%6,%7}, {%8,%9}, {%0,%1,%2,%3};"
        : "+f"(c[0]), "+f"(c[1]), "+f"(c[2]), "+f"(c[3])
        : "r"(a[0]), "r"(a[1]), "r"(a[2]), "r"(a[3]), "r"(b0), "r"(b1));
}
// fp32 pair -> bf16x2 hi + bf16x2 residual
__device__ __forceinline__ void split2(float v0, float v1, uint32_t& h, uint32_t& l) {
    __nv_bfloat162 hh = __floats2bfloat162_rn(v0, v1);
    float r0 = v0 - __bfloat162float(hh.x);
    float r1 = v1 - __bfloat162float(hh.y);
    __nv_bfloat162 ll = __floats2bfloat162_rn(r0, r1);
    h = *reinterpret_cast<uint32_t*>(&hh);
    l = *reinterpret_cast<uint32_t*>(&ll);
}
// byte offset of 16B chunk (row, ch) in a [rows x 64] bf16 tile, XOR-swizzled
#define SWZ(r, ch) (((r) << 7) | (((unsigned)((ch) ^ (r)) & 7u) << 4))

// ---------------------------------------------------------------------------
// fp32 -> (bf16 hi, bf16 lo) elementwise split, float4-vectorized
// ---------------------------------------------------------------------------
__global__ __launch_bounds__(256)
void split_kernel(const float* __restrict__ src,
                  __nv_bfloat16* __restrict__ hi, __nv_bfloat16* __restrict__ lo) {
    size_t i = (size_t)blockIdx.x * 256 + threadIdx.x;
    float4 v = ((const float4*)src)[i];
    uint32_t h0, l0, h1, l1;
    split2(v.x, v.y, h0, l0);
    split2(v.z, v.w, h1, l1);
    ((uint32_t*)hi)[2*i+0] = h0;  ((uint32_t*)hi)[2*i+1] = h1;
    ((uint32_t*)lo)[2*i+0] = l0;  ((uint32_t*)lo)[2*i+1] = l1;
}

// ---------------------------------------------------------------------------
// W[K,N] fp32 -> Wt[N,K] bf16 hi/lo (transpose + split)
// ---------------------------------------------------------------------------
__global__ __launch_bounds__(256)
void tsplit_kernel(const float* __restrict__ W,
                   __nv_bfloat16* __restrict__ Th, __nv_bfloat16* __restrict__ Tl) {
    __shared__ float sm[32][33];
    const int tx = threadIdx.x, ty = threadIdx.y;
    const int n0 = blockIdx.x * 32, k0 = blockIdx.y * 32;
#pragma unroll
    for (int r = ty; r < 32; r += 8)
        sm[r][tx] = W[(size_t)(k0 + r) * EMB + n0 + tx];
    __syncthreads();
#pragma unroll
    for (int r = ty; r < 32; r += 8) {
        float v = sm[tx][r];   // = W[k0+tx][n0+r]
        __nv_bfloat16 h = __float2bfloat16_rn(v);
        __nv_bfloat16 l = __float2bfloat16_rn(v - __bfloat162float(h));
        Th[(size_t)(n0 + r) * EMB + k0 + tx] = h;
        Tl[(size_t)(n0 + r) * EMB + k0 + tx] = l;
    }
}

// ---------------------------------------------------------------------------
// bf16x3 warp-MMA GEMM: C[M,1024] = (Ah+Al) @ (Bh+Bl)^T + bias
// B operands are [N,K] (pre-transposed W). 128x128 tile, 8 warps, warp 32x64.
// HEADOUT=1: split result to bf16 hi/lo, write [B,H,S,D] (Ch/Cl).
// HEADOUT=0: fp32 row-major to Co.
// ---------------------------------------------------------------------------
template<int HEADOUT>
__global__ __launch_bounds__(256, 2)
void gemm_mma(const __nv_bfloat16* __restrict__ Ah, const __nv_bfloat16* __restrict__ Al,
              const __nv_bfloat16* __restrict__ Bh, const __nv_bfloat16* __restrict__ Bl,
              const float* __restrict__ bias, float* __restrict__ Co,
              __nv_bfloat16* __restrict__ Ch, __nv_bfloat16* __restrict__ Cl) {
    extern __shared__ __align__(128) char smem[];
    char* pAh = smem;
    char* pAl = smem + 16384;
    char* pBh = smem + 32768;
    char* pBl = smem + 49152;
    const uint32_t sAh = smem_u32(pAh), sAl = smem_u32(pAl);
    const uint32_t sBh = smem_u32(pBh), sBl = smem_u32(pBl);
    const int t = threadIdx.x, lane = t & 31, w = t >> 5;
    const int wm = (w & 3) * 32, wn = (w >> 2) * 64;
    const int m0 = blockIdx.y << 7, n0 = blockIdx.x << 7;

    float c[2][8][4];
#pragma unroll
    for (int i = 0; i < 2; i++)
#pragma unroll
        for (int j = 0; j < 8; j++)
#pragma unroll
            for (int k = 0; k < 4; k++) c[i][j][k] = 0.f;

    for (int kc = 0; kc < EMB; kc += 64) {
        __syncthreads();
#pragma unroll
        for (int i = 0; i < 4; i++) {
            int idx = t + (i << 8);          // 0..1023
            int row = idx >> 3, ch = idx & 7;
            int so = SWZ(row, ch);
            size_t ga = (size_t)(m0 + row) * EMB + kc + (ch << 3);
            size_t gb = (size_t)(n0 + row) * EMB + kc + (ch << 3);
            *(uint4*)(pAh + so) = *(const uint4*)(Ah + ga);
            *(uint4*)(pAl + so) = *(const uint4*)(Al + ga);
            *(uint4*)(pBh + so) = *(const uint4*)(Bh + gb);
            *(uint4*)(pBl + so) = *(const uint4*)(Bl + gb);
        }
        __syncthreads();
#pragma unroll
        for (int s = 0; s < 4; s++) {
            const int ch = 2 * s + (lane >> 4);
            uint32_t ah[2][4], al[2][4];
#pragma unroll
            for (int mt = 0; mt < 2; mt++) {
                int r = wm + mt * 16 + (lane & 15);
                ldsm4(ah[mt], sAh + SWZ(r, ch));
                ldsm4(al[mt], sAl + SWZ(r, ch));
            }
#pragma unroll
            for (int g = 0; g < 4; g++) {
                int r = wn + g * 16 + (lane & 15);
                uint32_t bh[4], bl[4];
                ldsm4(bh, sBh + SWZ(r, ch));
                ldsm4(bl, sBl + SWZ(r, ch));
#pragma unroll
                for (int mt = 0; mt < 2; mt++) {
                    mma16816(c[mt][2*g],   ah[mt], bh[0], bh[2]);
                    mma16816(c[mt][2*g+1], ah[mt], bh[1], bh[3]);
                    mma16816(c[mt][2*g],   ah[mt], bl[0], bl[2]);
                    mma16816(c[mt][2*g+1], ah[mt], bl[1], bl[3]);
                    mma16816(c[mt][2*g],   al[mt], bh[0], bh[2]);
                    mma16816(c[mt][2*g+1], al[mt], bh[1], bh[3]);
                }
            }
        }
    }

    // epilogue
#pragma unroll
    for (int mt = 0; mt < 2; mt++) {
#pragma unroll
        for (int nt = 0; nt < 8; nt++) {
            const int col = n0 + wn + nt * 8 + ((lane & 3) << 1);
            const float b0 = bias[col], b1 = bias[col + 1];
            const int r0 = m0 + wm + mt * 16 + (lane >> 2);
#pragma unroll
            for (int half = 0; half < 2; half++) {
                const int r = r0 + half * 8;
                const float v0 = c[mt][nt][half*2+0] + b0;
                const float v1 = c[mt][nt][half*2+1] + b1;
                if (HEADOUT) {
                    uint32_t h2, l2;
                    split2(v0, v1, h2, l2);
                    const int bb = r >> 11, srow = r & 2047;
                    const int hd = col >> 6, d = col & 63;
                    const size_t off = (((size_t)(bb * NH + hd)) * SEQ + srow) * HD + d;
                    *(uint32_t*)(Ch + off) = h2;
                    *(uint32_t*)(Cl + off) = l2;
                } else {
                    *(float2*)(Co + (size_t)r * EMB + col) = make_float2(v0, v1);
                }
            }
        }
    }
}

// ---------------------------------------------------------------------------
// Flash attention on warp-MMA, bf16x3. Block = 128 queries (8 warps x m16),
// 64-key tiles, P kept in registers (C-frag -> A-frag), ldmatrix.trans for V.
// Writes output as bf16 hi/lo straight into g_xh/g_xl [B,S,E].
// ---------------------------------------------------------------------------
__global__ __launch_bounds__(256, 2)
void attn_mma(const int* __restrict__ mask) {
    extern __shared__ __align__(128) char smem[];
    char* pQh = smem;              // 128x64 bf16 = 16KB
    char* pQl = smem + 16384;
    char* pKh = smem + 32768;      // 64x64 bf16 = 8KB each
    char* pKl = smem + 40960;
    char* pVh = smem + 49152;
    char* pVl = smem + 57344;
    float* smb = (float*)(smem + 65536);   // 64 floats mask bias
    const uint32_t sQh = smem_u32(pQh), sQl = smem_u32(pQl);
    const uint32_t sKh = smem_u32(pKh), sKl = smem_u32(pKl);
    const uint32_t sVh = smem_u32(pVh), sVl = smem_u32(pVl);

    const int t = threadIdx.x, lane = t & 31, w = t >> 5;
    const int qb = blockIdx.x, h = blockIdx.y, b = blockIdx.z;
    const size_t base = ((size_t)(b * NH + h)) * SEQ * HD;

    // load Q tile (128 x 64, hi+lo)
#pragma unroll
    for (int i = 0; i < 4; i++) {
        int idx = t + (i << 8);
        int row = idx >> 3, ch = idx & 7;
        int so = SWZ(row, ch);
        size_t ga = base + (size_t)(qb * 128 + row) * HD + (ch << 3);
        *(uint4*)(pQh + so) = *(const uint4*)(g_Qh + ga);
        *(uint4*)(pQl + so) = *(const uint4*)(g_Ql + ga);
    }

    float o[8][4];
#pragma unroll
    for (int i = 0; i < 8; i++)
#pragma unroll
        for (int j = 0; j < 4; j++) o[i][j] = 0.f;
    float mrow[2] = {-INFINITY, -INFINITY};
    float lsum[2] = {0.f, 0.f};

    for (int kb = 0; kb < SEQ / 64; kb++) {
        __syncthreads();
#pragma unroll
        for (int i = 0; i < 2; i++) {
            int idx = t + (i << 8);          // 0..511
            int row = idx >> 3, ch = idx & 7;
            int so = SWZ(row, ch);
            size_t ga = base + (size_t)(kb * 64 + row) * HD + (ch << 3);
            *(uint4*)(pKh + so) = *(const uint4*)(g_Kh + ga);
            *(uint4*)(pKl + so) = *(const uint4*)(g_Kl + ga);
            *(uint4*)(pVh + so) = *(const uint4*)(g_Vh + ga);
            *(uint4*)(pVl + so) = *(const uint4*)(g_Vl + ga);
        }
        if (t < 64) smb[t] = mask[b * SEQ + kb * 64 + t] ? 0.f : -1.0e9f;
        __syncthreads();

        // ---- S = Q K^T (bf16x3) ----
        float c[8][4];
#pragma unroll
        for (int i = 0; i < 8; i++)
#pragma unroll
            for (int j = 0; j < 4; j++) c[i][j] = 0.f;
#pragma unroll
        for (int s = 0; s < 4; s++) {
            const int ch = 2 * s + (lane >> 4);
            uint32_t ah[4], al[4];
            const int rq = w * 16 + (lane & 15);
            ldsm4(ah, sQh + SWZ(rq, ch));
            ldsm4(al, sQl + SWZ(rq, ch));
#pragma unroll
            for (int g = 0; g < 4; g++) {
                const int rk = g * 16 + (lane & 15);
                uint32_t bh[4], bl[4];
                ldsm4(bh, sKh + SWZ(rk, ch));
                ldsm4(bl, sKl + SWZ(rk, ch));
                mma16816(c[2*g],   ah, bh[0], bh[2]);
                mma16816(c[2*g+1], ah, bh[1], bh[3]);
                mma16816(c[2*g],   ah, bl[0], bl[2]);
                mma16816(c[2*g+1], ah, bl[1], bl[3]);
                mma16816(c[2*g],   al, bh[0], bh[2]);
                mma16816(c[2*g+1], al, bh[1], bh[3]);
            }
        }

        // ---- scale + mask bias (fp32 makes -1e9 + s round to exactly -1e9) ----
        const int cb = (lane & 3) << 1;
#pragma unroll
        for (int nt = 0; nt < 8; nt++) {
            const float m0v = smb[nt * 8 + cb], m1v = smb[nt * 8 + cb + 1];
            c[nt][0] = fmaf(c[nt][0], 0.125f, m0v);
            c[nt][1] = fmaf(c[nt][1], 0.125f, m1v);
            c[nt][2] = fmaf(c[nt][2], 0.125f, m0v);
            c[nt][3] = fmaf(c[nt][3], 0.125f, m1v);
        }

        // ---- online softmax (rows split: A = lane>>2, B = +8) ----
        float mxA = -INFINITY, mxB = -INFINITY;
#pragma unroll
        for (int nt = 0; nt < 8; nt++) {
            mxA = fmaxf(mxA, fmaxf(c[nt][0], c[nt][1]));
            mxB = fmaxf(mxB, fmaxf(c[nt][2], c[nt][3]));
        }
#pragma unroll
        for (int off = 1; off < 4; off <<= 1) {
            mxA = fmaxf(mxA, __shfl_xor_sync(0xffffffffu, mxA, off));
            mxB = fmaxf(mxB, __shfl_xor_sync(0xffffffffu, mxB, off));
        }
        const float nmA = fmaxf(mrow[0], mxA), nmB = fmaxf(mrow[1], mxB);
        const float scA = __expf(mrow[0] - nmA), scB = __expf(mrow[1] - nmB);
        mrow[0] = nmA; mrow[1] = nmB;
        float sA = 0.f, sB = 0.f;
#pragma unroll
        for (int nt = 0; nt < 8; nt++) {
            c[nt][0] = __expf(c[nt][0] - nmA);
            c[nt][1] = __expf(c[nt][1] - nmA);
            c[nt][2] = __expf(c[nt][2] - nmB);
            c[nt][3] = __expf(c[nt][3] - nmB);
            sA += c[nt][0] + c[nt][1];
            sB += c[nt][2] + c[nt][3];
        }
#pragma unroll
        for (int off = 1; off < 4; off <<= 1) {
            sA += __shfl_xor_sync(0xffffffffu, sA, off);
            sB += __shfl_xor_sync(0xffffffffu, sB, off);
        }
        lsum[0] = lsum[0] * scA + sA;
        lsum[1] = lsum[1] * scB + sB;
#pragma unroll
        for (int nt = 0; nt < 8; nt++) {
            o[nt][0] *= scA; o[nt][1] *= scA;
            o[nt][2] *= scB; o[nt][3] *= scB;
        }

        // ---- O += P V (P in registers: C-frag -> A-frag; bf16x3) ----
#pragma unroll
        for (int kt = 0; kt < 4; kt++) {
            uint32_t ph[4], pl[4];
            split2(c[2*kt][0],   c[2*kt][1],   ph[0], pl[0]);
            split2(c[2*kt][2],   c[2*kt][3],   ph[1], pl[1]);
            split2(c[2*kt+1][0], c[2*kt+1][1], ph[2], pl[2]);
            split2(c[2*kt+1][2], c[2*kt+1][3], ph[3], pl[3]);
            const int rv = kt * 16 + (lane & 15);
#pragma unroll
            for (int g = 0; g < 4; g++) {
                const int chv = 2 * g + (lane >> 4);
                uint32_t vh[4], vl[4];
                ldsm4t(vh, sVh + SWZ(rv, chv));
                ldsm4t(vl, sVl + SWZ(rv, chv));
                mma16816(o[2*g],   ph, vh[0], vh[1]);
                mma16816(o[2*g+1], ph, vh[2], vh[3]);
                mma16816(o[2*g],   ph, vl[0], vl[1]);
                mma16816(o[2*g+1], ph, vl[2], vl[3]);
                mma16816(o[2*g],   pl, vh[0], vh[1]);
                mma16816(o[2*g+1], pl, vh[2], vh[3]);
            }
        }
    }

    // ---- epilogue: normalize, split to bf16 hi/lo, write [B,S,E] ----
    const float iA = 1.f / lsum[0], iB = 1.f / lsum[1];
    const int rA = qb * 128 + w * 16 + (lane >> 2);
    const int colb = (lane & 3) << 1;
#pragma unroll
    for (int nt = 0; nt < 8; nt++) {
        const int col = h * HD + nt * 8 + colb;
        uint32_t h2, l2;
        split2(o[nt][0] * iA, o[nt][1] * iA, h2, l2);
        size_t off = ((size_t)b * SEQ + rA) * EMB + col;
        *(uint32_t*)(g_xh + off) = h2;
        *(uint32_t*)(g_xl + off) = l2;
        split2(o[nt][2] * iB, o[nt][3] * iB, h2, l2);
        off = ((size_t)b * SEQ + rA + 8) * EMB + col;
        *(uint32_t*)(g_xh + off) = h2;
        *(uint32_t*)(g_xl + off) = l2;
    }
}

// ---------------------------------------------------------------------------
extern "C" void kernel_launch(void* const* d_in, const int* in_sizes, int n_in,
                              void* d_out, int out_size) {
    const float* x  = (const float*)d_in[0];
    const int*  mask = (const int*)d_in[1];
    const float* Wq = (const float*)d_in[2];
    const float* bq = (const float*)d_in[3];
    const float* Wk = (const float*)d_in[4];
    const float* bk = (const float*)d_in[5];
    const float* Wv = (const float*)d_in[6];
    const float* bv = (const float*)d_in[7];
    const float* Wo = (const float*)d_in[8];
    const float* bo = (const float*)d_in[9];

    __nv_bfloat16 *xh, *xl, *wh, *wl, *Qh, *Ql, *Kh, *Kl, *Vh, *Vl;
    cudaGetSymbolAddress((void**)&xh, g_xh);
    cudaGetSymbolAddress((void**)&xl, g_xl);
    cudaGetSymbolAddress((void**)&wh, g_wh);
    cudaGetSymbolAddress((void**)&wl, g_wl);
    cudaGetSymbolAddress((void**)&Qh, g_Qh);
    cudaGetSymbolAddress((void**)&Ql, g_Ql);
    cudaGetSymbolAddress((void**)&Kh, g_Kh);
    cudaGetSymbolAddress((void**)&Kl, g_Kl);
    cudaGetSymbolAddress((void**)&Vh, g_Vh);
    cudaGetSymbolAddress((void**)&Vl, g_Vl);
    const size_t WS = (size_t)EMB * EMB;

    cudaFuncSetAttribute(gemm_mma<1>, cudaFuncAttributeMaxDynamicSharedMemorySize, 65536);
    cudaFuncSetAttribute(gemm_mma<0>, cudaFuncAttributeMaxDynamicSharedMemorySize, 65536);
    cudaFuncSetAttribute(attn_mma,    cudaFuncAttributeMaxDynamicSharedMemorySize, 65536 + 256);

    // input split + weight transpose/split
    split_kernel<<<(MTOT*EMB)/4/256, 256>>>(x, xh, xl);
    tsplit_kernel<<<dim3(32,32), dim3(32,8)>>>(Wq, wh + 0*WS, wl + 0*WS);
    tsplit_kernel<<<dim3(32,32), dim3(32,8)>>>(Wk, wh + 1*WS, wl + 1*WS);
    tsplit_kernel<<<dim3(32,32), dim3(32,8)>>>(Wv, wh + 2*WS, wl + 2*WS);
    tsplit_kernel<<<dim3(32,32), dim3(32,8)>>>(Wo, wh + 3*WS, wl + 3*WS);

    // QKV projections (epilogues emit bf16 hi/lo in [B,H,S,D])
    dim3 gg(EMB/128, MTOT/128);   // (8, 64)
    gemm_mma<1><<<gg, 256, 65536>>>(xh, xl, wh + 0*WS, wl + 0*WS, bq, nullptr, Qh, Ql);
    gemm_mma<1><<<gg, 256, 65536>>>(xh, xl, wh + 1*WS, wl + 1*WS, bk, nullptr, Kh, Kl);
    gemm_mma<1><<<gg, 256, 65536>>>(xh, xl, wh + 2*WS, wl + 2*WS, bv, nullptr, Vh, Vl);

    // attention -> writes bf16 hi/lo activations into xh/xl ([B,S,E])
    attn_mma<<<dim3(SEQ/128, NH, BSZ), 256, 65536 + 256>>>(mask);

    // O projection -> fp32 d_out
    gemm_mma<0><<<gg, 256, 65536>>>(xh, xl, wh + 3*WS, wl + 3*WS, bo, (float*)d_out, nullptr, nullptr);
}

// round 6
// speedup vs baseline: 3.1548x; 1.1395x over previous
#include <cuda_runtime.h>
#include <cuda_bf16.h>
#include <math.h>
#include <stdint.h>

#define BSZ 4
#define SEQ 2048
#define EMB 1024
#define NH 16
#define HD 64
#define MTOT (BSZ*SEQ)   // 8192

// ---------------- scratch (__device__ globals; no allocs allowed) ----------
static __device__ __align__(256) __nv_bfloat16 g_xh[(size_t)MTOT*EMB];
static __device__ __align__(256) __nv_bfloat16 g_xl[(size_t)MTOT*EMB];
static __device__ __align__(256) __nv_bfloat16 g_wh[4][(size_t)EMB*EMB];
static __device__ __align__(256) __nv_bfloat16 g_wl[4][(size_t)EMB*EMB];
static __device__ __align__(256) __nv_bfloat16 g_Qh[(size_t)MTOT*EMB];
static __device__ __align__(256) __nv_bfloat16 g_Ql[(size_t)MTOT*EMB];
static __device__ __align__(256) __nv_bfloat16 g_Kh[(size_t)MTOT*EMB];
static __device__ __align__(256) __nv_bfloat16 g_Kl[(size_t)MTOT*EMB];
static __device__ __align__(256) __nv_bfloat16 g_Vh[(size_t)MTOT*EMB];
static __device__ __align__(256) __nv_bfloat16 g_Vl[(size_t)MTOT*EMB];

// ---------------- helpers --------------------------------------------------
__device__ __forceinline__ uint32_t smem_u32(const void* p) {
    uint32_t a;
    asm("{ .reg .u64 t; cvta.to.shared.u64 t, %1; cvt.u32.u64 %0, t; }"
        : "=r"(a) : "l"(p));
    return a;
}
__device__ __forceinline__ void cp16(uint32_t dst, const void* src) {
    asm volatile("cp.async.cg.shared.global [%0], [%1], 16;" :: "r"(dst), "l"(src));
}
#define CP_COMMIT() asm volatile("cp.async.commit_group;" ::: "memory")
#define CP_WAIT1()  asm volatile("cp.async.wait_group 1;" ::: "memory")
#define CP_WAIT0()  asm volatile("cp.async.wait_group 0;" ::: "memory")

__device__ __forceinline__ void ldsm4(uint32_t r[4], uint32_t a) {
    asm volatile("ldmatrix.sync.aligned.m8n8.x4.shared.b16 {%0,%1,%2,%3}, [%4];"
        : "=r"(r[0]), "=r"(r[1]), "=r"(r[2]), "=r"(r[3]) : "r"(a));
}
__device__ __forceinline__ void ldsm4t(uint32_t r[4], uint32_t a) {
    asm volatile("ldmatrix.sync.aligned.m8n8.x4.trans.shared.b16 {%0,%1,%2,%3}, [%4];"
        : "=r"(r[0]), "=r"(r[1]), "=r"(r[2]), "=r"(r[3]) : "r"(a));
}
__device__ __forceinline__ void mma16816(float c[4], const uint32_t a[4],
                                         uint32_t b0, uint32_t b1) {
    asm volatile("mma.sync.aligned.m16n8k16.row.col.f32.bf16.bf16.f32 "
        "{%0,%1,%2,%3}, {%4,%5,%6,%7}, {%8,%9}, {%0,%1,%2,%3};"
        : "+f"(c[0]), "+f"(c[1]), "+f"(c[2]), "+f"(c[3])
        : "r"(a[0]), "r"(a[1]), "r"(a[2]), "r"(a[3]), "r"(b0), "r"(b1));
}
__device__ __forceinline__ void split2(float v0, float v1, uint32_t& h, uint32_t& l) {
    __nv_bfloat162 hh = __floats2bfloat162_rn(v0, v1);
    float r0 = v0 - __bfloat162float(hh.x);
    float r1 = v1 - __bfloat162float(hh.y);
    __nv_bfloat162 ll = __floats2bfloat162_rn(r0, r1);
    h = *reinterpret_cast<uint32_t*>(&hh);
    l = *reinterpret_cast<uint32_t*>(&ll);
}
// byte offset of 16B chunk (row, ch) in a [rows x 64] bf16 tile, XOR-swizzled
#define SWZ(r, ch) (((r) << 7) | (((unsigned)((ch) ^ (r)) & 7u) << 4))

// ---------------------------------------------------------------------------
__global__ __launch_bounds__(256)
void split_kernel(const float* __restrict__ src,
                  __nv_bfloat16* __restrict__ hi, __nv_bfloat16* __restrict__ lo) {
    size_t i = (size_t)blockIdx.x * 256 + threadIdx.x;
    float4 v = ((const float4*)src)[i];
    uint32_t h0, l0, h1, l1;
    split2(v.x, v.y, h0, l0);
    split2(v.z, v.w, h1, l1);
    ((uint32_t*)hi)[2*i+0] = h0;  ((uint32_t*)hi)[2*i+1] = h1;
    ((uint32_t*)lo)[2*i+0] = l0;  ((uint32_t*)lo)[2*i+1] = l1;
}

__global__ __launch_bounds__(256)
void tsplit_kernel(const float* __restrict__ W,
                   __nv_bfloat16* __restrict__ Th, __nv_bfloat16* __restrict__ Tl) {
    __shared__ float sm[32][33];
    const int tx = threadIdx.x, ty = threadIdx.y;
    const int n0 = blockIdx.x * 32, k0 = blockIdx.y * 32;
#pragma unroll
    for (int r = ty; r < 32; r += 8)
        sm[r][tx] = W[(size_t)(k0 + r) * EMB + n0 + tx];
    __syncthreads();
#pragma unroll
    for (int r = ty; r < 32; r += 8) {
        float v = sm[tx][r];
        __nv_bfloat16 h = __float2bfloat16_rn(v);
        __nv_bfloat16 l = __float2bfloat16_rn(v - __bfloat162float(h));
        Th[(size_t)(n0 + r) * EMB + k0 + tx] = h;
        Tl[(size_t)(n0 + r) * EMB + k0 + tx] = l;
    }
}

// ---------------------------------------------------------------------------
// bf16x3 warp-MMA GEMM, cp.async 3-stage pipeline, one __syncthreads/chunk.
// HEADOUT=1 (fused QKV): grid.z selects W/bias/output; writes bf16 hi/lo
// [B,H,S,D]. HEADOUT=0: fp32 row-major to Co.
// Stage layout (64KB): Ah 0 | Al 16K | Bh 32K | Bl 48K.
// ---------------------------------------------------------------------------
template<int HEADOUT>
__global__ __launch_bounds__(256, 1)
void gemm_mma(const __nv_bfloat16* __restrict__ Ah, const __nv_bfloat16* __restrict__ Al,
              const __nv_bfloat16* __restrict__ WhBase, const __nv_bfloat16* __restrict__ WlBase,
              const float* __restrict__ b0p, const float* __restrict__ b1p,
              const float* __restrict__ b2p, float* __restrict__ Co,
              __nv_bfloat16* __restrict__ C0h, __nv_bfloat16* __restrict__ C0l,
              __nv_bfloat16* __restrict__ C1h, __nv_bfloat16* __restrict__ C1l,
              __nv_bfloat16* __restrict__ C2h, __nv_bfloat16* __restrict__ C2l) {
    extern __shared__ __align__(128) char smem[];
    const uint32_t sb = smem_u32(smem);
    const int t = threadIdx.x, lane = t & 31, w = t >> 5;
    const int wm = (w & 3) * 32, wn = (w >> 2) * 64;
    const int m0 = blockIdx.y << 7, n0 = blockIdx.x << 7;
    const int z = HEADOUT ? blockIdx.z : 0;

    const __nv_bfloat16* Bh = WhBase + (size_t)z * EMB * EMB;
    const __nv_bfloat16* Bl = WlBase + (size_t)z * EMB * EMB;
    const float* bias = (z == 0) ? b0p : (z == 1 ? b1p : b2p);
    __nv_bfloat16* Ch = (z == 0) ? C0h : (z == 1 ? C1h : C2h);
    __nv_bfloat16* Cl = (z == 0) ? C0l : (z == 1 ? C1l : C2l);

    // issue one 64-wide K-chunk into stage st
    auto issue = [&](int kb, int st) {
        const uint32_t s0 = sb + st * 65536;
        const int kc = kb << 6;
#pragma unroll
        for (int i = 0; i < 4; i++) {
            int idx = t + (i << 8);
            int row = idx >> 3, ch = idx & 7;
            int so = SWZ(row, ch);
            size_t ga = (size_t)(m0 + row) * EMB + kc + (ch << 3);
            size_t gb = (size_t)(n0 + row) * EMB + kc + (ch << 3);
            cp16(s0 +         so, Ah + ga);
            cp16(s0 + 16384 + so, Al + ga);
            cp16(s0 + 32768 + so, Bh + gb);
            cp16(s0 + 49152 + so, Bl + gb);
        }
    };

    float c[2][8][4];
#pragma unroll
    for (int i = 0; i < 2; i++)
#pragma unroll
        for (int j = 0; j < 8; j++)
#pragma unroll
            for (int k = 0; k < 4; k++) c[i][j][k] = 0.f;

    issue(0, 0); CP_COMMIT();
    issue(1, 1); CP_COMMIT();

    for (int kb = 0; kb < 16; kb++) {
        CP_WAIT1();
        __syncthreads();
        if (kb + 2 < 16) issue(kb + 2, (kb + 2) % 3);
        CP_COMMIT();   // empty group near tail keeps wait_group accounting valid

        const uint32_t s0 = sb + (kb % 3) * 65536;
        const uint32_t sAh = s0, sAl = s0 + 16384, sBh = s0 + 32768, sBl = s0 + 49152;
#pragma unroll
        for (int s = 0; s < 4; s++) {
            const int ch = 2 * s + (lane >> 4);
            uint32_t ah[2][4], al[2][4];
#pragma unroll
            for (int mt = 0; mt < 2; mt++) {
                int r = wm + mt * 16 + (lane & 15);
                ldsm4(ah[mt], sAh + SWZ(r, ch));
                ldsm4(al[mt], sAl + SWZ(r, ch));
            }
#pragma unroll
            for (int g = 0; g < 4; g++) {
                int r = wn + g * 16 + (lane & 15);
                uint32_t bh[4], bl[4];
                ldsm4(bh, sBh + SWZ(r, ch));
                ldsm4(bl, sBl + SWZ(r, ch));
#pragma unroll
                for (int mt = 0; mt < 2; mt++) {
                    mma16816(c[mt][2*g],   ah[mt], bh[0], bh[2]);
                    mma16816(c[mt][2*g+1], ah[mt], bh[1], bh[3]);
                    mma16816(c[mt][2*g],   ah[mt], bl[0], bl[2]);
                    mma16816(c[mt][2*g+1], ah[mt], bl[1], bl[3]);
                    mma16816(c[mt][2*g],   al[mt], bh[0], bh[2]);
                    mma16816(c[mt][2*g+1], al[mt], bh[1], bh[3]);
                }
            }
        }
    }

    // epilogue
#pragma unroll
    for (int mt = 0; mt < 2; mt++) {
#pragma unroll
        for (int nt = 0; nt < 8; nt++) {
            const int col = n0 + wn + nt * 8 + ((lane & 3) << 1);
            const float b0 = bias[col], b1 = bias[col + 1];
            const int r0 = m0 + wm + mt * 16 + (lane >> 2);
#pragma unroll
            for (int half = 0; half < 2; half++) {
                const int r = r0 + half * 8;
                const float v0 = c[mt][nt][half*2+0] + b0;
                const float v1 = c[mt][nt][half*2+1] + b1;
                if (HEADOUT) {
                    uint32_t h2, l2;
                    split2(v0, v1, h2, l2);
                    const int bb = r >> 11, srow = r & 2047;
                    const int hd = col >> 6, d = col & 63;
                    const size_t off = (((size_t)(bb * NH + hd)) * SEQ + srow) * HD + d;
                    *(uint32_t*)(Ch + off) = h2;
                    *(uint32_t*)(Cl + off) = l2;
                } else {
                    *(float2*)(Co + (size_t)r * EMB + col) = make_float2(v0, v1);
                }
            }
        }
    }
}

// ---------------------------------------------------------------------------
// Flash attention, warp-MMA bf16x3, cp.async 2-stage K/V pipeline,
// one __syncthreads per key-tile. Q + full mask bias row prefetched once.
// smem: Q 32KB | KV stage0 32KB | KV stage1 32KB | mask bias 8KB.
// KV stage layout: Kh 0 | Kl 8K | Vh 16K | Vl 24K.
// ---------------------------------------------------------------------------
__global__ __launch_bounds__(256, 2)
void attn_mma(const int* __restrict__ mask) {
    extern __shared__ __align__(128) char smem[];
    char* pQh = smem;                       // 128x64 bf16 x2 (hi/lo) = 32KB
    char* pQl = smem + 16384;
    const uint32_t sQh = smem_u32(pQh), sQl = smem_u32(pQl);
    const uint32_t sKV = smem_u32(smem + 32768);
    float* smb = (float*)(smem + 98304);    // 2048 floats mask bias

    const int t = threadIdx.x, lane = t & 31, w = t >> 5;
    const int qb = blockIdx.x, h = blockIdx.y, b = blockIdx.z;
    const size_t base = ((size_t)(b * NH + h)) * SEQ * HD;

    auto issue_kv = [&](int kb, int st) {
        const uint32_t s0 = sKV + st * 32768;
#pragma unroll
        for (int i = 0; i < 2; i++) {
            int idx = t + (i << 8);          // 0..511
            int row = idx >> 3, ch = idx & 7;
            int so = SWZ(row, ch);
            size_t ga = base + (size_t)(kb * 64 + row) * HD + (ch << 3);
            cp16(s0 +         so, g_Kh + ga);
            cp16(s0 +  8192 + so, g_Kl + ga);
            cp16(s0 + 16384 + so, g_Vh + ga);
            cp16(s0 + 24576 + so, g_Vl + ga);
        }
    };

    // prologue: Q tile + mask bias + KV chunk 0
#pragma unroll
    for (int i = 0; i < 4; i++) {
        int idx = t + (i << 8);
        int row = idx >> 3, ch = idx & 7;
        int so = SWZ(row, ch);
        size_t ga = base + (size_t)(qb * 128 + row) * HD + (ch << 3);
        cp16(sQh + so, g_Qh + ga);
        cp16(sQl + so, g_Ql + ga);
    }
    {
        const int4* m4 = (const int4*)(mask + b * SEQ);
#pragma unroll
        for (int i = 0; i < 2; i++) {
            int idx = t + (i << 8);          // 0..511
            int4 mm = m4[idx];
            smb[idx*4+0] = mm.x ? 0.f : -1.0e9f;
            smb[idx*4+1] = mm.y ? 0.f : -1.0e9f;
            smb[idx*4+2] = mm.z ? 0.f : -1.0e9f;
            smb[idx*4+3] = mm.w ? 0.f : -1.0e9f;
        }
    }
    issue_kv(0, 0); CP_COMMIT();

    float o[8][4];
#pragma unroll
    for (int i = 0; i < 8; i++)
#pragma unroll
        for (int j = 0; j < 4; j++) o[i][j] = 0.f;
    float mrow[2] = {-INFINITY, -INFINITY};
    float lsum[2] = {0.f, 0.f};

    for (int kb = 0; kb < SEQ / 64; kb++) {
        CP_WAIT0();
        __syncthreads();
        if (kb + 1 < SEQ / 64) issue_kv(kb + 1, (kb + 1) & 1);
        CP_COMMIT();

        const uint32_t s0 = sKV + (kb & 1) * 32768;
        const uint32_t sKh = s0, sKl = s0 + 8192, sVh = s0 + 16384, sVl = s0 + 24576;

        // ---- S = Q K^T (bf16x3) ----
        float c[8][4];
#pragma unroll
        for (int i = 0; i < 8; i++)
#pragma unroll
            for (int j = 0; j < 4; j++) c[i][j] = 0.f;
#pragma unroll
        for (int s = 0; s < 4; s++) {
            const int ch = 2 * s + (lane >> 4);
            uint32_t ah[4], al[4];
            const int rq = w * 16 + (lane & 15);
            ldsm4(ah, sQh + SWZ(rq, ch));
            ldsm4(al, sQl + SWZ(rq, ch));
#pragma unroll
            for (int g = 0; g < 4; g++) {
                const int rk = g * 16 + (lane & 15);
                uint32_t bh[4], bl[4];
                ldsm4(bh, sKh + SWZ(rk, ch));
                ldsm4(bl, sKl + SWZ(rk, ch));
                mma16816(c[2*g],   ah, bh[0], bh[2]);
                mma16816(c[2*g+1], ah, bh[1], bh[3]);
                mma16816(c[2*g],   ah, bl[0], bl[2]);
                mma16816(c[2*g+1], ah, bl[1], bl[3]);
                mma16816(c[2*g],   al, bh[0], bh[2]);
                mma16816(c[2*g+1], al, bh[1], bh[3]);
            }
        }

        // ---- scale + mask bias ----
        const int cb = (lane & 3) << 1;
        const float* mbt = smb + kb * 64;
#pragma unroll
        for (int nt = 0; nt < 8; nt++) {
            const float m0v = mbt[nt * 8 + cb], m1v = mbt[nt * 8 + cb + 1];
            c[nt][0] = fmaf(c[nt][0], 0.125f, m0v);
            c[nt][1] = fmaf(c[nt][1], 0.125f, m1v);
            c[nt][2] = fmaf(c[nt][2], 0.125f, m0v);
            c[nt][3] = fmaf(c[nt][3], 0.125f, m1v);
        }

        // ---- online softmax ----
        float mxA = -INFINITY, mxB = -INFINITY;
#pragma unroll
        for (int nt = 0; nt < 8; nt++) {
            mxA = fmaxf(mxA, fmaxf(c[nt][0], c[nt][1]));
            mxB = fmaxf(mxB, fmaxf(c[nt][2], c[nt][3]));
        }
#pragma unroll
        for (int off = 1; off < 4; off <<= 1) {
            mxA = fmaxf(mxA, __shfl_xor_sync(0xffffffffu, mxA, off));
            mxB = fmaxf(mxB, __shfl_xor_sync(0xffffffffu, mxB, off));
        }
        const float nmA = fmaxf(mrow[0], mxA), nmB = fmaxf(mrow[1], mxB);
        const float scA = __expf(mrow[0] - nmA), scB = __expf(mrow[1] - nmB);
        mrow[0] = nmA; mrow[1] = nmB;
        float sA = 0.f, sB = 0.f;
#pragma unroll
        for (int nt = 0; nt < 8; nt++) {
            c[nt][0] = __expf(c[nt][0] - nmA);
            c[nt][1] = __expf(c[nt][1] - nmA);
            c[nt][2] = __expf(c[nt][2] - nmB);
            c[nt][3] = __expf(c[nt][3] - nmB);
            sA += c[nt][0] + c[nt][1];
            sB += c[nt][2] + c[nt][3];
        }
#pragma unroll
        for (int off = 1; off < 4; off <<= 1) {
            sA += __shfl_xor_sync(0xffffffffu, sA, off);
            sB += __shfl_xor_sync(0xffffffffu, sB, off);
        }
        lsum[0] = lsum[0] * scA + sA;
        lsum[1] = lsum[1] * scB + sB;
#pragma unroll
        for (int nt = 0; nt < 8; nt++) {
            o[nt][0] *= scA; o[nt][1] *= scA;
            o[nt][2] *= scB; o[nt][3] *= scB;
        }

        // ---- O += P V ----
#pragma unroll
        for (int kt = 0; kt < 4; kt++) {
            uint32_t ph[4], pl[4];
            split2(c[2*kt][0],   c[2*kt][1],   ph[0], pl[0]);
            split2(c[2*kt][2],   c[2*kt][3],   ph[1], pl[1]);
            split2(c[2*kt+1][0], c[2*kt+1][1], ph[2], pl[2]);
            split2(c[2*kt+1][2], c[2*kt+1][3], ph[3], pl[3]);
            const int rv = kt * 16 + (lane & 15);
#pragma unroll
            for (int g = 0; g < 4; g++) {
                const int chv = 2 * g + (lane >> 4);
                uint32_t vh[4], vl[4];
                ldsm4t(vh, sVh + SWZ(rv, chv));
                ldsm4t(vl, sVl + SWZ(rv, chv));
                mma16816(o[2*g],   ph, vh[0], vh[1]);
                mma16816(o[2*g+1], ph, vh[2], vh[3]);
                mma16816(o[2*g],   ph, vl[0], vl[1]);
                mma16816(o[2*g+1], ph, vl[2], vl[3]);
                mma16816(o[2*g],   pl, vh[0], vh[1]);
                mma16816(o[2*g+1], pl, vh[2], vh[3]);
            }
        }
    }

    // ---- epilogue: normalize, split, write bf16 hi/lo [B,S,E] ----
    const float iA = 1.f / lsum[0], iB = 1.f / lsum[1];
    const int rA = qb * 128 + w * 16 + (lane >> 2);
    const int colb = (lane & 3) << 1;
#pragma unroll
    for (int nt = 0; nt < 8; nt++) {
        const int col = h * HD + nt * 8 + colb;
        uint32_t h2, l2;
        split2(o[nt][0] * iA, o[nt][1] * iA, h2, l2);
        size_t off = ((size_t)b * SEQ + rA) * EMB + col;
        *(uint32_t*)(g_xh + off) = h2;
        *(uint32_t*)(g_xl + off) = l2;
        split2(o[nt][2] * iB, o[nt][3] * iB, h2, l2);
        off = ((size_t)b * SEQ + rA + 8) * EMB + col;
        *(uint32_t*)(g_xh + off) = h2;
        *(uint32_t*)(g_xl + off) = l2;
    }
}

// ---------------------------------------------------------------------------
extern "C" void kernel_launch(void* const* d_in, const int* in_sizes, int n_in,
                              void* d_out, int out_size) {
    const float* x  = (const float*)d_in[0];
    const int*  mask = (const int*)d_in[1];
    const float* Wq = (const float*)d_in[2];
    const float* bq = (const float*)d_in[3];
    const float* Wk = (const float*)d_in[4];
    const float* bk = (const float*)d_in[5];
    const float* Wv = (const float*)d_in[6];
    const float* bv = (const float*)d_in[7];
    const float* Wo = (const float*)d_in[8];
    const float* bo = (const float*)d_in[9];

    __nv_bfloat16 *xh, *xl, *wh, *wl, *Qh, *Ql, *Kh, *Kl, *Vh, *Vl;
    cudaGetSymbolAddress((void**)&xh, g_xh);
    cudaGetSymbolAddress((void**)&xl, g_xl);
    cudaGetSymbolAddress((void**)&wh, g_wh);
    cudaGetSymbolAddress((void**)&wl, g_wl);
    cudaGetSymbolAddress((void**)&Qh, g_Qh);
    cudaGetSymbolAddress((void**)&Ql, g_Ql);
    cudaGetSymbolAddress((void**)&Kh, g_Kh);
    cudaGetSymbolAddress((void**)&Kl, g_Kl);
    cudaGetSymbolAddress((void**)&Vh, g_Vh);
    cudaGetSymbolAddress((void**)&Vl, g_Vl);
    const size_t WS = (size_t)EMB * EMB;

    const int GEMM_SMEM = 3 * 65536;           // 192KB
    const int ATTN_SMEM = 98304 + 8192;        // 104KB
    cudaFuncSetAttribute(gemm_mma<1>, cudaFuncAttributeMaxDynamicSharedMemorySize, GEMM_SMEM);
    cudaFuncSetAttribute(gemm_mma<0>, cudaFuncAttributeMaxDynamicSharedMemorySize, GEMM_SMEM);
    cudaFuncSetAttribute(attn_mma,    cudaFuncAttributeMaxDynamicSharedMemorySize, ATTN_SMEM);

    // input split + weight transpose/split
    split_kernel<<<(MTOT*EMB)/4/256, 256>>>(x, xh, xl);
    tsplit_kernel<<<dim3(32,32), dim3(32,8)>>>(Wq, wh + 0*WS, wl + 0*WS);
    tsplit_kernel<<<dim3(32,32), dim3(32,8)>>>(Wk, wh + 1*WS, wl + 1*WS);
    tsplit_kernel<<<dim3(32,32), dim3(32,8)>>>(Wv, wh + 2*WS, wl + 2*WS);
    tsplit_kernel<<<dim3(32,32), dim3(32,8)>>>(Wo, wh + 3*WS, wl + 3*WS);

    // fused QKV projection (z = 0,1,2 -> Q,K,V), bf16 hi/lo out in [B,H,S,D]
    gemm_mma<1><<<dim3(EMB/128, MTOT/128, 3), 256, GEMM_SMEM>>>(
        xh, xl, wh, wl, bq, bk, bv, nullptr, Qh, Ql, Kh, Kl, Vh, Vl);

    // attention -> bf16 hi/lo activations into xh/xl ([B,S,E])
    attn_mma<<<dim3(SEQ/128, NH, BSZ), 256, ATTN_SMEM>>>(mask);

    // O projection -> fp32 d_out
    gemm_mma<0><<<dim3(EMB/128, MTOT/128, 1), 256, GEMM_SMEM>>>(
        xh, xl, wh + 3*WS, wl + 3*WS, bo, bo, bo, (float*)d_out,
        nullptr, nullptr, nullptr, nullptr, nullptr, nullptr);
}